// round 3
// baseline (speedup 1.0000x reference)
#include <cuda_runtime.h>
#include <cstdint>

#define NNODES 100000
#define NEDGES 1600000
#define FIN    128
#define HID    64
#define NCLS   40

// ---------------- device scratch (allocation-free) ----------------
__device__ int   g_hist[NNODES];              // in-degree (excl self-loop)
__device__ int   g_cnt[NNODES];               // bucket fill cursors
__device__ int   g_offs[NNODES + 1];          // CSR row offsets (by dst)
__device__ int   g_csr_src[NEDGES];           // src per CSR slot
__device__ float g_csr_norm[NEDGES];          // dinv[src]*dinv[dst] per slot
__device__ float g_dinv[NNODES];
__device__ float g_h1[(size_t)NNODES * HID];  // x @ W1
__device__ float g_agg1[(size_t)NNODES * HID];
__device__ float g_h2[(size_t)NNODES * NCLS]; // relu(agg1) @ W2

// ---------------- helpers ----------------
typedef unsigned long long u64;
__device__ __forceinline__ u64 ffma2(u64 a, u64 b, u64 c) {
    u64 d;
    asm("fma.rn.f32x2 %0, %1, %2, %3;" : "=l"(d) : "l"(a), "l"(b), "l"(c));
    return d;
}
__device__ __forceinline__ u64 pack2(float x) {
    u64 d;
    asm("mov.b64 %0, {%1, %1};" : "=l"(d) : "f"(x));
    return d;
}
union F2 { u64 u; float2 f; };
union W4 { float4 v; struct { u64 lo, hi; } u; };

// ---------------- CSR build ----------------
__global__ void k_zero() {
    int i = blockIdx.x * blockDim.x + threadIdx.x;
    if (i < NNODES) { g_hist[i] = 0; g_cnt[i] = 0; }
}
__global__ void k_hist(const int* __restrict__ dst) {
    int e = blockIdx.x * blockDim.x + threadIdx.x;
    if (e < NEDGES) atomicAdd(&g_hist[dst[e]], 1);
}
// single-block exclusive scan + dinv
__global__ void __launch_bounds__(1024) k_scan() {
    __shared__ int sums[1024];
    const int SEG = (NNODES + 1023) / 1024;   // 98
    const int t = threadIdx.x;
    const int lo = t * SEG;
    const int hi = (lo + SEG < NNODES) ? lo + SEG : NNODES;
    int s = 0;
    for (int i = lo; i < hi; i++) s += g_hist[i];
    sums[t] = s;
    __syncthreads();
    // Hillis-Steele inclusive scan
    for (int ofs = 1; ofs < 1024; ofs <<= 1) {
        int v = (t >= ofs) ? sums[t - ofs] : 0;
        __syncthreads();
        sums[t] += v;
        __syncthreads();
    }
    int run = (t == 0) ? 0 : sums[t - 1];
    for (int i = lo; i < hi; i++) {
        int h = g_hist[i];
        g_offs[i] = run;
        run += h;
        g_dinv[i] = rsqrtf((float)(h + 1));   // deg includes self-loop
    }
    if (t == 1023) g_offs[NNODES] = NEDGES;
}
__global__ void k_fill(const int* __restrict__ src, const int* __restrict__ dst) {
    int e = blockIdx.x * blockDim.x + threadIdx.x;
    if (e >= NEDGES) return;
    int s = src[e], d = dst[e];
    int r = atomicAdd(&g_cnt[d], 1);
    int pos = g_offs[d] + r;
    g_csr_src[pos]  = s;
    g_csr_norm[pos] = g_dinv[s] * g_dinv[d];
}

// ---------------- GEMM1: h1 = x @ W1 ----------------
// 256 threads, 128-row tile, thread = 4 rows x 8 cols (f32x2 FMA).
#define XS_PITCH 132
__global__ void __launch_bounds__(256) k_gemm1(const float* __restrict__ x,
                                               const float* __restrict__ W1) {
    __shared__ float xs[128 * XS_PITCH];  // 67.6 KB
    __shared__ float ws[FIN * HID];       // 32 KB
    const int tid  = threadIdx.x;
    const int row0 = blockIdx.x * 128;

    {
        const float4* wsrc = (const float4*)W1;
        float4* wdst = (float4*)ws;
        #pragma unroll
        for (int i = 0; i < 8; i++) wdst[tid + i * 256] = wsrc[tid + i * 256];
    }
    {
        #pragma unroll
        for (int i = 0; i < 16; i++) {
            int f = tid + i * 256;            // [0, 4096)
            int r = f >> 5;
            int o = (f & 31) << 2;
            float4 v = make_float4(0.f, 0.f, 0.f, 0.f);
            if (row0 + r < NNODES) v = *(const float4*)(x + (size_t)(row0 + r) * FIN + o);
            *(float4*)(xs + r * XS_PITCH + o) = v;
        }
    }
    __syncthreads();

    const int rp = tid >> 3;              // 0..31 -> rows rp*4..rp*4+3
    const int cg = tid & 7;               // 8 cols
    const float* wcol = ws + cg * 8;

    u64 acc[4][4];
    #pragma unroll
    for (int r = 0; r < 4; r++)
        #pragma unroll
        for (int j = 0; j < 4; j++) acc[r][j] = 0ull;

    const float* xr = xs + (rp * 4) * XS_PITCH;

    #pragma unroll 2
    for (int k = 0; k < FIN; k += 4) {
        float4 xa[4];
        #pragma unroll
        for (int r = 0; r < 4; r++)
            xa[r] = *(const float4*)(xr + r * XS_PITCH + k);
        #pragma unroll
        for (int kk = 0; kk < 4; kk++) {
            W4 w0, w1;
            w0.v = *(const float4*)(wcol + (k + kk) * HID);
            w1.v = *(const float4*)(wcol + (k + kk) * HID + 4);
            #pragma unroll
            for (int r = 0; r < 4; r++) {
                u64 xv = pack2((&xa[r].x)[kk]);
                acc[r][0] = ffma2(w0.u.lo, xv, acc[r][0]);
                acc[r][1] = ffma2(w0.u.hi, xv, acc[r][1]);
                acc[r][2] = ffma2(w1.u.lo, xv, acc[r][2]);
                acc[r][3] = ffma2(w1.u.hi, xv, acc[r][3]);
            }
        }
    }

    #pragma unroll
    for (int r = 0; r < 4; r++) {
        int row = row0 + rp * 4 + r;
        if (row >= NNODES) continue;
        F2 a0, a1, a2, a3;
        a0.u = acc[r][0]; a1.u = acc[r][1]; a2.u = acc[r][2]; a3.u = acc[r][3];
        float* hp = g_h1 + (size_t)row * HID + cg * 8;
        *(float4*)(hp)     = make_float4(a0.f.x, a0.f.y, a1.f.x, a1.f.y);
        *(float4*)(hp + 4) = make_float4(a2.f.x, a2.f.y, a3.f.x, a3.f.y);
    }
}

// ---------------- agg1: per-node gather (no atomics) ----------------
// half-warp (16 lanes) per node; lane j owns float4 chunk j of HID=64.
__global__ void __launch_bounds__(256) k_agg1(const float* __restrict__ b1) {
    int n = blockIdx.x * 16 + (threadIdx.x >> 4);
    if (n >= NNODES) return;
    int j = threadIdx.x & 15;
    int p0 = g_offs[n], p1 = g_offs[n + 1];
    float4 acc = make_float4(0.f, 0.f, 0.f, 0.f);
    int p = p0;
    for (; p + 2 <= p1; p += 2) {
        int   s0 = g_csr_src[p],     s1 = g_csr_src[p + 1];
        float w0 = g_csr_norm[p],    w1 = g_csr_norm[p + 1];
        float4 v0 = *(const float4*)(g_h1 + (size_t)s0 * HID + j * 4);
        float4 v1 = *(const float4*)(g_h1 + (size_t)s1 * HID + j * 4);
        acc.x = fmaf(v0.x, w0, acc.x); acc.y = fmaf(v0.y, w0, acc.y);
        acc.z = fmaf(v0.z, w0, acc.z); acc.w = fmaf(v0.w, w0, acc.w);
        acc.x = fmaf(v1.x, w1, acc.x); acc.y = fmaf(v1.y, w1, acc.y);
        acc.z = fmaf(v1.z, w1, acc.z); acc.w = fmaf(v1.w, w1, acc.w);
    }
    if (p < p1) {
        int   s0 = g_csr_src[p];
        float w0 = g_csr_norm[p];
        float4 v0 = *(const float4*)(g_h1 + (size_t)s0 * HID + j * 4);
        acc.x = fmaf(v0.x, w0, acc.x); acc.y = fmaf(v0.y, w0, acc.y);
        acc.z = fmaf(v0.z, w0, acc.z); acc.w = fmaf(v0.w, w0, acc.w);
    }
    // self-loop + bias
    float di = g_dinv[n];
    float dd = di * di;
    float4 sv = *(const float4*)(g_h1 + (size_t)n * HID + j * 4);
    float4 bb = *(const float4*)(b1 + j * 4);
    acc.x = fmaf(sv.x, dd, acc.x) + bb.x;
    acc.y = fmaf(sv.y, dd, acc.y) + bb.y;
    acc.z = fmaf(sv.z, dd, acc.z) + bb.z;
    acc.w = fmaf(sv.w, dd, acc.w) + bb.w;
    *(float4*)(g_agg1 + (size_t)n * HID + j * 4) = acc;
}

// ---------------- GEMM2: h2 = relu(agg1) @ W2 ----------------
#define XS2_PITCH 68
__global__ void __launch_bounds__(256) k_gemm2(const float* __restrict__ W2) {
    __shared__ float xs[64 * XS2_PITCH];
    __shared__ float ws[HID * 64];
    const int tid  = threadIdx.x;
    const int row0 = blockIdx.x * 64;

    #pragma unroll
    for (int i = 0; i < 16; i++) {
        int idx = tid + i * 256;
        int k = idx >> 6, c = idx & 63;
        ws[idx] = (c < NCLS) ? W2[k * NCLS + c] : 0.0f;
    }
    #pragma unroll
    for (int i = 0; i < 4; i++) {
        int f = tid + i * 256;
        int r = f >> 4;
        int o = (f & 15) << 2;
        float4 v = make_float4(0.f, 0.f, 0.f, 0.f);
        if (row0 + r < NNODES) {
            float4 a = *(const float4*)(g_agg1 + (size_t)(row0 + r) * HID + o);
            v = make_float4(fmaxf(a.x, 0.f), fmaxf(a.y, 0.f),
                            fmaxf(a.z, 0.f), fmaxf(a.w, 0.f));
        }
        *(float4*)(xs + r * XS2_PITCH + o) = v;
    }
    __syncthreads();

    const int rp = tid >> 3;
    const int cg = tid & 7;
    if (cg >= 5) return;                  // cols 40..63 are padding
    const int r0 = rp * 2;
    const float* xr0 = xs + r0 * XS2_PITCH;
    const float* xr1 = xs + (r0 + 1) * XS2_PITCH;
    const float* wcol = ws + cg * 8;

    u64 acc[2][4];
    #pragma unroll
    for (int r = 0; r < 2; r++)
        #pragma unroll
        for (int j = 0; j < 4; j++) acc[r][j] = 0ull;

    #pragma unroll 4
    for (int k = 0; k < HID; k += 4) {
        float4 xa = *(const float4*)(xr0 + k);
        float4 xb = *(const float4*)(xr1 + k);
        #pragma unroll
        for (int kk = 0; kk < 4; kk++) {
            u64 xa2 = pack2((&xa.x)[kk]);
            u64 xb2 = pack2((&xb.x)[kk]);
            W4 w0, w1;
            w0.v = *(const float4*)(wcol + (k + kk) * 64);
            w1.v = *(const float4*)(wcol + (k + kk) * 64 + 4);
            acc[0][0] = ffma2(w0.u.lo, xa2, acc[0][0]);
            acc[0][1] = ffma2(w0.u.hi, xa2, acc[0][1]);
            acc[0][2] = ffma2(w1.u.lo, xa2, acc[0][2]);
            acc[0][3] = ffma2(w1.u.hi, xa2, acc[0][3]);
            acc[1][0] = ffma2(w0.u.lo, xb2, acc[1][0]);
            acc[1][1] = ffma2(w0.u.hi, xb2, acc[1][1]);
            acc[1][2] = ffma2(w1.u.lo, xb2, acc[1][2]);
            acc[1][3] = ffma2(w1.u.hi, xb2, acc[1][3]);
        }
    }

    #pragma unroll
    for (int r = 0; r < 2; r++) {
        int row = row0 + r0 + r;
        if (row >= NNODES) continue;
        F2 a0, a1, a2, a3;
        a0.u = acc[r][0]; a1.u = acc[r][1]; a2.u = acc[r][2]; a3.u = acc[r][3];
        float* hp = g_h2 + (size_t)row * NCLS + cg * 8;
        *(float4*)(hp)     = make_float4(a0.f.x, a0.f.y, a1.f.x, a1.f.y);
        *(float4*)(hp + 4) = make_float4(a2.f.x, a2.f.y, a3.f.x, a3.f.y);
    }
}

// ---------------- agg2: per-node gather into out ----------------
// half-warp per node; lanes 0..9 own float4 chunks of NCLS=40.
__global__ void __launch_bounds__(256) k_agg2(const float* __restrict__ b2,
                                              float* __restrict__ out) {
    int n = blockIdx.x * 16 + (threadIdx.x >> 4);
    if (n >= NNODES) return;
    int j = threadIdx.x & 15;
    if (j >= 10) return;
    int p0 = g_offs[n], p1 = g_offs[n + 1];
    float4 acc = make_float4(0.f, 0.f, 0.f, 0.f);
    int p = p0;
    for (; p + 2 <= p1; p += 2) {
        int   s0 = g_csr_src[p],     s1 = g_csr_src[p + 1];
        float w0 = g_csr_norm[p],    w1 = g_csr_norm[p + 1];
        float4 v0 = *(const float4*)(g_h2 + (size_t)s0 * NCLS + j * 4);
        float4 v1 = *(const float4*)(g_h2 + (size_t)s1 * NCLS + j * 4);
        acc.x = fmaf(v0.x, w0, acc.x); acc.y = fmaf(v0.y, w0, acc.y);
        acc.z = fmaf(v0.z, w0, acc.z); acc.w = fmaf(v0.w, w0, acc.w);
        acc.x = fmaf(v1.x, w1, acc.x); acc.y = fmaf(v1.y, w1, acc.y);
        acc.z = fmaf(v1.z, w1, acc.z); acc.w = fmaf(v1.w, w1, acc.w);
    }
    if (p < p1) {
        int   s0 = g_csr_src[p];
        float w0 = g_csr_norm[p];
        float4 v0 = *(const float4*)(g_h2 + (size_t)s0 * NCLS + j * 4);
        acc.x = fmaf(v0.x, w0, acc.x); acc.y = fmaf(v0.y, w0, acc.y);
        acc.z = fmaf(v0.z, w0, acc.z); acc.w = fmaf(v0.w, w0, acc.w);
    }
    float di = g_dinv[n];
    float dd = di * di;
    float4 sv = *(const float4*)(g_h2 + (size_t)n * NCLS + j * 4);
    float4 bb = *(const float4*)(b2 + j * 4);
    acc.x = fmaf(sv.x, dd, acc.x) + bb.x;
    acc.y = fmaf(sv.y, dd, acc.y) + bb.y;
    acc.z = fmaf(sv.z, dd, acc.z) + bb.z;
    acc.w = fmaf(sv.w, dd, acc.w) + bb.w;
    *(float4*)(out + (size_t)n * NCLS + j * 4) = acc;
}

// ---------------- launch ----------------
extern "C" void kernel_launch(void* const* d_in, const int* in_sizes, int n_in,
                              void* d_out, int out_size) {
    const float* x   = (const float*)d_in[0];
    const int*   ei  = (const int*)d_in[1];
    const float* W1  = (const float*)d_in[2];
    const float* b1  = (const float*)d_in[3];
    const float* W2  = (const float*)d_in[4];
    const float* b2  = (const float*)d_in[5];
    float* out = (float*)d_out;

    const int* src = ei;
    const int* dst = ei + NEDGES;

    // CSR build (also yields dinv)
    k_zero<<<(NNODES + 255) / 256, 256>>>();
    k_hist<<<(NEDGES + 255) / 256, 256>>>(dst);
    k_scan<<<1, 1024>>>();
    k_fill<<<(NEDGES + 255) / 256, 256>>>(src, dst);

    // layer 1
    cudaFuncSetAttribute(k_gemm1, cudaFuncAttributeMaxDynamicSharedMemorySize, 0);
    k_gemm1<<<(NNODES + 127) / 128, 256>>>(x, W1);
    k_agg1<<<(NNODES + 15) / 16, 256>>>(b1);

    // layer 2
    k_gemm2<<<(NNODES + 63) / 64, 256>>>(W2);
    k_agg2<<<(NNODES + 15) / 16, 256>>>(b2, out);
}